// round 1
// baseline (speedup 1.0000x reference)
#include <cuda_runtime.h>
#include <cuda_bf16.h>
#include <cstddef>

// ---------------------------------------------------------------------------
// Attention_87428354277788  — fp32 baseline, f32x2-packed SGEMM + fused
// flash-style attention with pre-gathered relative-position bias.
//
// Shapes: b=128, n=256, e=768, h=12, d=64.
// Inputs (metadata order):
//   0: x              [128,256,768] f32
//   1: W_qkv          [768,2304]    f32
//   2: b_qkv          [2304]        f32
//   3: W_out          [768,768]     f32
//   4: b_out          [768]         f32
//   5: rel_bias_table [961,12]      f32
//   6: rel_pos_ids    [65536]       i32
// Output: [128,256,768] f32
// ---------------------------------------------------------------------------

typedef unsigned long long u64;

// Scratch (device globals — no allocations allowed)
__device__ float g_qkv[75497472];   // [32768, 2304]  (q|k|v fused, 302 MB)
__device__ float g_attn[25165824];  // [32768, 768]   attention output
__device__ float g_bias[786432];    // [12, 256, 256] dense rel-pos bias

// ---------------------------------------------------------------------------
// f32x2 helpers (sm_100+ packed fp32 pipe — 2x FFMA throughput vs 3-reg FFMA)
// ---------------------------------------------------------------------------
__device__ __forceinline__ u64 pack2(float x, float y) {
    u64 r; asm("mov.b64 %0, {%1, %2};" : "=l"(r) : "f"(x), "f"(y)); return r;
}
__device__ __forceinline__ u64 fma2(u64 a, u64 b, u64 c) {
    u64 d; asm("fma.rn.f32x2 %0, %1, %2, %3;" : "=l"(d) : "l"(a), "l"(b), "l"(c));
    return d;
}
__device__ __forceinline__ float2 unpack2(u64 v) {
    float2 f; asm("mov.b64 {%0, %1}, %2;" : "=f"(f.x), "=f"(f.y) : "l"(v)); return f;
}

// ---------------------------------------------------------------------------
// Dense bias gather: biasmat[h][q][k] = table[ids[q*256+k]][h]
// ---------------------------------------------------------------------------
__global__ void bias_gather_kernel(const int* __restrict__ ids,
                                   const float* __restrict__ table,
                                   float* __restrict__ biasmat)
{
    int pos = blockIdx.x * 256 + threadIdx.x;   // 65536 positions
    int id = ids[pos];
#pragma unroll
    for (int h = 0; h < 12; h++)
        biasmat[h * 65536 + pos] = table[id * 12 + h];
}

// ---------------------------------------------------------------------------
// SGEMM: C[M,N] = A[M,K] @ B[K,N] + bias[N]
// Block tile 128x128, BK=8, 256 threads, 8x8 per thread, f32x2 accumulators.
// Requires M%128==0, N%128==0, K%8==0 (true for all our shapes).
// ---------------------------------------------------------------------------
__global__ __launch_bounds__(256, 2) void sgemm_kernel(
    const float* __restrict__ A, const float* __restrict__ B,
    const float* __restrict__ bias, float* __restrict__ C,
    int M, int N, int K)
{
    __shared__ float As[8][128];   // As[k][m] (A tile transposed)
    __shared__ float Bs[8][128];   // Bs[k][n]

    const int tid = threadIdx.x;
    const int bx = blockIdx.x, by = blockIdx.y;
    const int ty = tid >> 4, tx = tid & 15;

    const int arow = tid >> 1;            // 0..127
    const int acol = (tid & 1) << 2;      // 0 or 4
    const int brow = tid >> 5;            // 0..7
    const int bcol = (tid & 31) << 2;     // 0..124

    const float* Ag = A + (size_t)(by * 128 + arow) * K + acol;
    const float* Bg = B + (size_t)brow * N + bx * 128 + bcol;

    u64 acc[8][4];
#pragma unroll
    for (int i = 0; i < 8; i++)
#pragma unroll
        for (int j = 0; j < 4; j++) acc[i][j] = 0ULL;

    for (int k0 = 0; k0 < K; k0 += 8) {
        float4 av = *(const float4*)(Ag + k0);
        float4 bv = *(const float4*)(Bg + (size_t)k0 * N);
        __syncthreads();   // protect previous iteration's smem reads
        As[acol + 0][arow] = av.x;
        As[acol + 1][arow] = av.y;
        As[acol + 2][arow] = av.z;
        As[acol + 3][arow] = av.w;
        *(float4*)&Bs[brow][bcol] = bv;
        __syncthreads();

#pragma unroll
        for (int kk = 0; kk < 8; kk++) {
            float a[8];
            *(float4*)(a)     = *(const float4*)&As[kk][ty * 8];
            *(float4*)(a + 4) = *(const float4*)&As[kk][ty * 8 + 4];
            const u64* bp = (const u64*)&Bs[kk][tx * 8];
            u64 b2[4];
#pragma unroll
            for (int j = 0; j < 4; j++) b2[j] = bp[j];
#pragma unroll
            for (int i = 0; i < 8; i++) {
                u64 a2 = pack2(a[i], a[i]);
#pragma unroll
                for (int j = 0; j < 4; j++) acc[i][j] = fma2(a2, b2[j], acc[i][j]);
            }
        }
    }

    const int colbase = bx * 128 + tx * 8;
#pragma unroll
    for (int i = 0; i < 8; i++) {
        size_t row = (size_t)(by * 128 + ty * 8 + i);
        float* cp = C + row * N + colbase;
#pragma unroll
        for (int j = 0; j < 4; j++) {
            float2 v = unpack2(acc[i][j]);
            v.x += bias[colbase + 2 * j];
            v.y += bias[colbase + 2 * j + 1];
            *(float2*)(cp + 2 * j) = v;
        }
    }
}

// ---------------------------------------------------------------------------
// Fused attention: per block = (q-tile of 64 rows, head h, batch b).
// Online softmax over 4 key tiles of 64. 256 threads:
//   thread (tyy=tid>>4, txx=tid&15) owns q rows r0=tyy*4..+3,
//   score keys {txx+16j}, output cols txx*4..+3.
// ---------------------------------------------------------------------------
__global__ __launch_bounds__(256) void attn_kernel(
    const float* __restrict__ qkv, const float* __restrict__ biasmat,
    float* __restrict__ attn_out)
{
    extern __shared__ float sm[];
    const int P = 68;                       // padded row stride (floats)
    float* Qs = sm;                         // [64][68]
    float* Ks = sm + 64 * P;                // [64][68]
    float* Vs = sm + 2 * 64 * P;            // [64][68]
    float* Ss = sm + 3 * 64 * P;            // [64][68]  P^T: Ss[key][row]

    const int qt = blockIdx.x, h = blockIdx.y, b = blockIdx.z;
    const int tid = threadIdx.x;
    const int tyy = tid >> 4, txx = tid & 15;
    const int r0 = tyy << 2;
    const int q0 = qt << 6;

    const size_t RS = 2304;
    const float* qg  = qkv + (size_t)(b * 256 + q0) * RS + h * 64;
    const float* kg0 = qkv + (size_t)(b * 256) * RS + 768 + h * 64;
    const float* vg0 = kg0 + 768;

    // Load Q tile [64 x 64]
#pragma unroll
    for (int l = 0; l < 4; l++) {
        int f = tid + (l << 8);
        int i = f >> 4, dd = (f & 15) << 2;
        *(float4*)(Qs + i * P + dd) = *(const float4*)(qg + (size_t)i * RS + dd);
    }

    float m[4], lsum[4], o[4][4];
#pragma unroll
    for (int i = 0; i < 4; i++) {
        m[i] = -1e30f; lsum[i] = 0.f;
#pragma unroll
        for (int j = 0; j < 4; j++) o[i][j] = 0.f;
    }

    const float* bb = biasmat + (size_t)h * 65536 + (size_t)q0 * 256;

    for (int kt = 0; kt < 4; kt++) {
        __syncthreads();   // previous tile's smem fully consumed
        const float* kg = kg0 + (size_t)(kt * 64) * RS;
        const float* vg = vg0 + (size_t)(kt * 64) * RS;
#pragma unroll
        for (int l = 0; l < 4; l++) {
            int f = tid + (l << 8);
            int i = f >> 4, dd = (f & 15) << 2;
            *(float4*)(Ks + i * P + dd) = *(const float4*)(kg + (size_t)i * RS + dd);
            *(float4*)(Vs + i * P + dd) = *(const float4*)(vg + (size_t)i * RS + dd);
        }
        __syncthreads();

        // --- scores: s[i][j] = Q[r0+i] . K[txx+16j] ---
        float s[4][4];
#pragma unroll
        for (int i = 0; i < 4; i++)
#pragma unroll
            for (int j = 0; j < 4; j++) s[i][j] = 0.f;

#pragma unroll
        for (int d4 = 0; d4 < 16; d4++) {
            float4 a[4], kv[4];
#pragma unroll
            for (int i = 0; i < 4; i++)
                a[i] = *(const float4*)(Qs + (r0 + i) * P + (d4 << 2));
#pragma unroll
            for (int j = 0; j < 4; j++)
                kv[j] = *(const float4*)(Ks + (txx + (j << 4)) * P + (d4 << 2));
#pragma unroll
            for (int i = 0; i < 4; i++)
#pragma unroll
                for (int j = 0; j < 4; j++)
                    s[i][j] += a[i].x * kv[j].x + a[i].y * kv[j].y +
                               a[i].z * kv[j].z + a[i].w * kv[j].w;
        }

        // --- bias + online softmax (row reduction across 16 lanes) ---
#pragma unroll
        for (int i = 0; i < 4; i++) {
            float tm = -1e30f;
#pragma unroll
            for (int j = 0; j < 4; j++) {
                float bv = bb[(r0 + i) * 256 + kt * 64 + txx + (j << 4)];
                s[i][j] = fmaf(s[i][j], 0.125f, bv);   // scale = 64^-0.5
                tm = fmaxf(tm, s[i][j]);
            }
            tm = fmaxf(tm, __shfl_xor_sync(0xffffffffu, tm, 1));
            tm = fmaxf(tm, __shfl_xor_sync(0xffffffffu, tm, 2));
            tm = fmaxf(tm, __shfl_xor_sync(0xffffffffu, tm, 4));
            tm = fmaxf(tm, __shfl_xor_sync(0xffffffffu, tm, 8));
            float mn = fmaxf(m[i], tm);
            float corr = __expf(m[i] - mn);
            m[i] = mn;
            float ps = 0.f;
#pragma unroll
            for (int j = 0; j < 4; j++) {
                s[i][j] = __expf(s[i][j] - mn);
                ps += s[i][j];
            }
            ps += __shfl_xor_sync(0xffffffffu, ps, 1);
            ps += __shfl_xor_sync(0xffffffffu, ps, 2);
            ps += __shfl_xor_sync(0xffffffffu, ps, 4);
            ps += __shfl_xor_sync(0xffffffffu, ps, 8);
            lsum[i] = lsum[i] * corr + ps;
#pragma unroll
            for (int j = 0; j < 4; j++) o[i][j] *= corr;
        }

        // --- stage P^T to smem ---
#pragma unroll
        for (int j = 0; j < 4; j++)
#pragma unroll
            for (int i = 0; i < 4; i++)
                Ss[(txx + (j << 4)) * P + r0 + i] = s[i][j];
        __syncthreads();

        // --- PV: o[i][j] += P[r0+i][k] * V[k][txx*4+j] ---
#pragma unroll 8
        for (int k = 0; k < 64; k++) {
            float4 pv = *(const float4*)(Ss + k * P + r0);
            float4 vv = *(const float4*)(Vs + k * P + (txx << 2));
            o[0][0] += pv.x * vv.x; o[0][1] += pv.x * vv.y; o[0][2] += pv.x * vv.z; o[0][3] += pv.x * vv.w;
            o[1][0] += pv.y * vv.x; o[1][1] += pv.y * vv.y; o[1][2] += pv.y * vv.z; o[1][3] += pv.y * vv.w;
            o[2][0] += pv.z * vv.x; o[2][1] += pv.z * vv.y; o[2][2] += pv.z * vv.z; o[2][3] += pv.z * vv.w;
            o[3][0] += pv.w * vv.x; o[3][1] += pv.w * vv.y; o[3][2] += pv.w * vv.z; o[3][3] += pv.w * vv.w;
        }
    }

    // --- normalize and store: attn_out[token][h*64 + c] ---
    float* og = attn_out + (size_t)(b * 256 + q0) * 768 + h * 64 + (txx << 2);
#pragma unroll
    for (int i = 0; i < 4; i++) {
        float inv = 1.0f / lsum[i];
        float4 w = make_float4(o[i][0] * inv, o[i][1] * inv,
                               o[i][2] * inv, o[i][3] * inv);
        *(float4*)(og + (size_t)(r0 + i) * 768) = w;
    }
}

// ---------------------------------------------------------------------------
extern "C" void kernel_launch(void* const* d_in, const int* in_sizes, int n_in,
                              void* d_out, int out_size)
{
    const float* x     = (const float*)d_in[0];
    const float* Wqkv  = (const float*)d_in[1];
    const float* bqkv  = (const float*)d_in[2];
    const float* Wout  = (const float*)d_in[3];
    const float* bout  = (const float*)d_in[4];
    const float* table = (const float*)d_in[5];
    const int*   ids   = (const int*)d_in[6];
    float* out = (float*)d_out;

    float *qkv, *attn, *bias;
    cudaGetSymbolAddress((void**)&qkv,  g_qkv);
    cudaGetSymbolAddress((void**)&attn, g_attn);
    cudaGetSymbolAddress((void**)&bias, g_bias);

    const int ATTN_SMEM = 4 * 64 * 68 * 4;   // 69632 B dynamic
    cudaFuncSetAttribute(attn_kernel,
                         cudaFuncAttributeMaxDynamicSharedMemorySize, ATTN_SMEM);

    // 1) dense rel-pos bias [12,256,256]
    bias_gather_kernel<<<256, 256>>>(ids, table, bias);

    // 2) fused QKV projection: [32768,768] @ [768,2304] + b_qkv
    sgemm_kernel<<<dim3(2304 / 128, 32768 / 128), 256>>>(
        x, Wqkv, bqkv, qkv, 32768, 2304, 768);

    // 3) fused attention with rel-pos bias + softmax
    attn_kernel<<<dim3(4, 12, 128), 256, ATTN_SMEM>>>(qkv, bias, attn);

    // 4) output projection: [32768,768] @ [768,768] + b_out
    sgemm_kernel<<<dim3(768 / 128, 32768 / 128), 256>>>(
        attn, Wout, bout, out, 32768, 768, 768);
}

// round 3
// speedup vs baseline: 2.0594x; 2.0594x over previous
#include <cuda_runtime.h>
#include <cuda_bf16.h>
#include <cstdint>
#include <cstddef>

// ---------------------------------------------------------------------------
// Attention_87428354277788 — R3: split-bf16 mma.sync GEMMs (harness ptxas
// targets sm_103 without 'a' -> no tcgen05; HMMA via mma.sync instead)
// + fused fp32 flash attention with pre-gathered relative-position bias.
//
// Shapes: b=128, n=256, e=768, h=12, d=64.
// ---------------------------------------------------------------------------

typedef unsigned long long u64;
typedef __nv_bfloat16 bf16;

// Scratch (device globals — no allocations allowed)
__device__ float g_qkv[75497472];      // [32768, 2304]
__device__ float g_attn[25165824];     // [32768, 768]
__device__ float g_bias[786432];       // [12, 256, 256]
__device__ bf16  g_ah[25165824];       // A hi  (x, then attn)  [32768,768]
__device__ bf16  g_al[25165824];       // A lo
__device__ bf16  g_bqh[1769472];       // WqkvT hi [2304,768]
__device__ bf16  g_bql[1769472];       // WqkvT lo
__device__ bf16  g_boh[589824];        // WoutT hi [768,768]
__device__ bf16  g_bol[589824];        // WoutT lo

// ---------------------------------------------------------------------------
// PTX helpers (all portable to non-'a' sm_103 target)
// ---------------------------------------------------------------------------
__device__ __forceinline__ uint32_t smem_u32(const void* p) {
    uint32_t a;
    asm("{ .reg .u64 t; cvta.to.shared.u64 t, %1; cvt.u32.u64 %0, t; }"
        : "=r"(a) : "l"(p));
    return a;
}
__device__ __forceinline__ void cp16(uint32_t s, const void* g) {
    asm volatile("cp.async.cg.shared.global [%0], [%1], 16;" :: "r"(s), "l"(g));
}
#define CP_COMMIT() asm volatile("cp.async.commit_group;" ::: "memory")
#define CP_WAIT0()  asm volatile("cp.async.wait_group 0;" ::: "memory")

__device__ __forceinline__ void ldsm4(uint32_t* r, uint32_t addr) {
    asm volatile("ldmatrix.sync.aligned.m8n8.x4.shared.b16 {%0,%1,%2,%3}, [%4];"
        : "=r"(r[0]), "=r"(r[1]), "=r"(r[2]), "=r"(r[3]) : "r"(addr));
}
__device__ __forceinline__ void mma_bf16(float* c, const uint32_t* a,
                                         const uint32_t* b) {
    asm volatile(
        "mma.sync.aligned.m16n8k16.row.col.f32.bf16.bf16.f32 "
        "{%0,%1,%2,%3}, {%4,%5,%6,%7}, {%8,%9}, {%0,%1,%2,%3};"
        : "+f"(c[0]), "+f"(c[1]), "+f"(c[2]), "+f"(c[3])
        : "r"(a[0]), "r"(a[1]), "r"(a[2]), "r"(a[3]), "r"(b[0]), "r"(b[1]));
}

// ---------------------------------------------------------------------------
// Split fp32 -> bf16 hi/lo (vectorized)
// ---------------------------------------------------------------------------
__global__ void split_kernel(const float* __restrict__ in,
                             bf16* __restrict__ hi, bf16* __restrict__ lo,
                             int n4)
{
    int i = blockIdx.x * 256 + threadIdx.x;
    if (i >= n4) return;
    float4 v = ((const float4*)in)[i];
    bf16 h0 = __float2bfloat16_rn(v.x);
    bf16 h1 = __float2bfloat16_rn(v.y);
    bf16 h2 = __float2bfloat16_rn(v.z);
    bf16 h3 = __float2bfloat16_rn(v.w);
    bf16 l0 = __float2bfloat16_rn(v.x - __bfloat162float(h0));
    bf16 l1 = __float2bfloat16_rn(v.y - __bfloat162float(h1));
    bf16 l2 = __float2bfloat16_rn(v.z - __bfloat162float(h2));
    bf16 l3 = __float2bfloat16_rn(v.w - __bfloat162float(h3));
    ((ushort4*)hi)[i] = make_ushort4(__bfloat16_as_ushort(h0), __bfloat16_as_ushort(h1),
                                     __bfloat16_as_ushort(h2), __bfloat16_as_ushort(h3));
    ((ushort4*)lo)[i] = make_ushort4(__bfloat16_as_ushort(l0), __bfloat16_as_ushort(l1),
                                     __bfloat16_as_ushort(l2), __bfloat16_as_ushort(l3));
}

// ---------------------------------------------------------------------------
// Split + transpose: W [R][C] fp32 -> outh/outl [C][R] bf16
// ---------------------------------------------------------------------------
__global__ void split_transpose_kernel(const float* __restrict__ in,
                                       bf16* __restrict__ outh,
                                       bf16* __restrict__ outl, int R, int C)
{
    __shared__ float t[32][33];
    int c0 = blockIdx.x * 32, r0 = blockIdx.y * 32;
#pragma unroll
    for (int i = threadIdx.y; i < 32; i += 8)
        t[i][threadIdx.x] = in[(size_t)(r0 + i) * C + c0 + threadIdx.x];
    __syncthreads();
#pragma unroll
    for (int i = threadIdx.y; i < 32; i += 8) {
        float v = t[threadIdx.x][i];
        bf16 h = __float2bfloat16_rn(v);
        bf16 l = __float2bfloat16_rn(v - __bfloat162float(h));
        size_t o = (size_t)(c0 + i) * R + r0 + threadIdx.x;
        outh[o] = h; outl[o] = l;
    }
}

// ---------------------------------------------------------------------------
// Dense bias gather: biasmat[h][q][k] = table[ids[q*256+k]][h]
// ---------------------------------------------------------------------------
__global__ void bias_gather_kernel(const int* __restrict__ ids,
                                   const float* __restrict__ table,
                                   float* __restrict__ biasmat)
{
    int pos = blockIdx.x * 256 + threadIdx.x;
    int id = ids[pos];
#pragma unroll
    for (int h = 0; h < 12; h++)
        biasmat[h * 65536 + pos] = table[id * 12 + h];
}

// ---------------------------------------------------------------------------
// Split-bf16 HMMA GEMM: C[M,N] = A[M,K]@BT[N,K]^T + bias, 3-term split.
// CTA 128x128, BK=32, 8 warps (2M x 4N), cp.async double-buffered.
// SMEM stage: 4 parts (Ah,Al,Bh,Bl), each 128 rows x 32 halves @ 80B stride.
// ---------------------------------------------------------------------------
#define RSB   80            // smem row stride bytes
#define PARTB 10240         // 128*80
#define STG   40960         // 4 parts
#define GSM   (2*STG)       // 80 KB

__global__ __launch_bounds__(256, 2) void hgemm_kernel(
    const bf16* __restrict__ Ah, const bf16* __restrict__ Al,
    const bf16* __restrict__ Bh, const bf16* __restrict__ Bl,
    const float* __restrict__ bias, float* __restrict__ C,
    int M, int N, int K)
{
    extern __shared__ char smraw[];
    const uint32_t sbase = smem_u32(smraw);
    const int tid = threadIdx.x;
    const int lane = tid & 31;
    const int wid = tid >> 5;
    const int warp_m = wid & 1;      // 2 warps over M
    const int warp_n = wid >> 1;     // 4 warps over N
    const int m0 = blockIdx.y * 128;
    const int n0 = blockIdx.x * 128;

    const bf16* gbase[4];
    gbase[0] = Ah + (size_t)m0 * K;
    gbase[1] = Al + (size_t)m0 * K;
    gbase[2] = Bh + (size_t)n0 * K;
    gbase[3] = Bl + (size_t)n0 * K;

    // ldmatrix per-lane byte offsets
    const uint32_t a_lane = (uint32_t)(((lane & 7) + ((lane >> 3) & 1) * 8) * RSB
                          + (lane >> 4) * 16 + warp_m * 64 * RSB);
    const uint32_t b_lane = (uint32_t)(((lane & 7) + (lane >> 4) * 8) * RSB
                          + ((lane >> 3) & 1) * 16 + warp_n * 32 * RSB);

    float acc[4][4][4];
#pragma unroll
    for (int i = 0; i < 4; i++)
#pragma unroll
        for (int j = 0; j < 4; j++)
#pragma unroll
            for (int q = 0; q < 4; q++) acc[i][j][q] = 0.f;

    const int nch = K >> 5;   // 24

    // ---- loader lambda-ish macro ----
#define LOAD_STAGE(ch) do {                                                  \
        const int k0_ = (ch) << 5;                                           \
        const uint32_t sst = sbase + ((ch) & 1) * STG;                       \
        _Pragma("unroll")                                                    \
        for (int t = 0; t < 8; t++) {                                        \
            const int part = t >> 1;                                         \
            const int row = ((t << 6) + (tid >> 2)) & 127;                   \
            const int seg = tid & 3;                                         \
            const bf16* g = gbase[part] + (size_t)row * K + k0_ + seg * 8;   \
            cp16(sst + part * PARTB + row * RSB + seg * 16, g);              \
        }                                                                    \
        CP_COMMIT();                                                         \
    } while (0)

    LOAD_STAGE(0);

    for (int ch = 0; ch < nch; ch++) {
        CP_WAIT0();
        __syncthreads();
        if (ch + 1 < nch) LOAD_STAGE(ch + 1);

        const uint32_t sbuf = sbase + (ch & 1) * STG;
        const uint32_t sAh = sbuf + a_lane;
        const uint32_t sAl = sbuf + PARTB + a_lane;
        const uint32_t sBh = sbuf + 2 * PARTB + b_lane;
        const uint32_t sBl = sbuf + 3 * PARTB + b_lane;

#pragma unroll
        for (int ko = 0; ko < 2; ko++) {
            const uint32_t kb = ko * 32;   // 16 halves = 32 bytes
            uint32_t bh[2][4], bl[2][4];
#pragma unroll
            for (int nt16 = 0; nt16 < 2; nt16++) {
                ldsm4(bh[nt16], sBh + nt16 * (16 * RSB) + kb);
                ldsm4(bl[nt16], sBl + nt16 * (16 * RSB) + kb);
            }
#pragma unroll
            for (int mt = 0; mt < 4; mt++) {
                uint32_t ah[4], al[4];
                ldsm4(ah, sAh + mt * (16 * RSB) + kb);
                ldsm4(al, sAl + mt * (16 * RSB) + kb);
#pragma unroll
                for (int nt16 = 0; nt16 < 2; nt16++) {
                    mma_bf16(acc[mt][2 * nt16],     ah, &bh[nt16][0]);
                    mma_bf16(acc[mt][2 * nt16 + 1], ah, &bh[nt16][2]);
                    mma_bf16(acc[mt][2 * nt16],     ah, &bl[nt16][0]);
                    mma_bf16(acc[mt][2 * nt16 + 1], ah, &bl[nt16][2]);
                    mma_bf16(acc[mt][2 * nt16],     al, &bh[nt16][0]);
                    mma_bf16(acc[mt][2 * nt16 + 1], al, &bh[nt16][2]);
                }
            }
        }
        __syncthreads();  // all warps done with sbuf before loader overwrites
    }

    // ---- epilogue ----
    const int quad = lane >> 2, tq = lane & 3;
#pragma unroll
    for (int mt = 0; mt < 4; mt++) {
        const int r = m0 + warp_m * 64 + mt * 16 + quad;
#pragma unroll
        for (int nt = 0; nt < 4; nt++) {
            const int c = n0 + warp_n * 32 + nt * 8 + tq * 2;
            const float b0 = bias[c], b1 = bias[c + 1];
            float* cp = C + (size_t)r * N + c;
            float2 v0 = make_float2(acc[mt][nt][0] + b0, acc[mt][nt][1] + b1);
            float2 v1 = make_float2(acc[mt][nt][2] + b0, acc[mt][nt][3] + b1);
            *(float2*)cp = v0;
            *(float2*)(cp + 8 * (size_t)N) = v1;
        }
    }
#undef LOAD_STAGE
}

// ---------------------------------------------------------------------------
// Fused attention (unchanged — fp32, passed R1)
// ---------------------------------------------------------------------------
__global__ __launch_bounds__(256) void attn_kernel(
    const float* __restrict__ qkv, const float* __restrict__ biasmat,
    float* __restrict__ attn_out)
{
    extern __shared__ float sm[];
    const int P = 68;
    float* Qs = sm;
    float* Ks = sm + 64 * P;
    float* Vs = sm + 2 * 64 * P;
    float* Ss = sm + 3 * 64 * P;

    const int qt = blockIdx.x, h = blockIdx.y, b = blockIdx.z;
    const int tid = threadIdx.x;
    const int tyy = tid >> 4, txx = tid & 15;
    const int r0 = tyy << 2;
    const int q0 = qt << 6;

    const size_t RS = 2304;
    const float* qg  = qkv + (size_t)(b * 256 + q0) * RS + h * 64;
    const float* kg0 = qkv + (size_t)(b * 256) * RS + 768 + h * 64;
    const float* vg0 = kg0 + 768;

#pragma unroll
    for (int l = 0; l < 4; l++) {
        int f = tid + (l << 8);
        int i = f >> 4, dd = (f & 15) << 2;
        *(float4*)(Qs + i * P + dd) = *(const float4*)(qg + (size_t)i * RS + dd);
    }

    float m[4], lsum[4], o[4][4];
#pragma unroll
    for (int i = 0; i < 4; i++) {
        m[i] = -1e30f; lsum[i] = 0.f;
#pragma unroll
        for (int j = 0; j < 4; j++) o[i][j] = 0.f;
    }

    const float* bb = biasmat + (size_t)h * 65536 + (size_t)q0 * 256;

    for (int kt = 0; kt < 4; kt++) {
        __syncthreads();
        const float* kg = kg0 + (size_t)(kt * 64) * RS;
        const float* vg = vg0 + (size_t)(kt * 64) * RS;
#pragma unroll
        for (int l = 0; l < 4; l++) {
            int f = tid + (l << 8);
            int i = f >> 4, dd = (f & 15) << 2;
            *(float4*)(Ks + i * P + dd) = *(const float4*)(kg + (size_t)i * RS + dd);
            *(float4*)(Vs + i * P + dd) = *(const float4*)(vg + (size_t)i * RS + dd);
        }
        __syncthreads();

        float s[4][4];
#pragma unroll
        for (int i = 0; i < 4; i++)
#pragma unroll
            for (int j = 0; j < 4; j++) s[i][j] = 0.f;

#pragma unroll
        for (int d4 = 0; d4 < 16; d4++) {
            float4 a[4], kv[4];
#pragma unroll
            for (int i = 0; i < 4; i++)
                a[i] = *(const float4*)(Qs + (r0 + i) * P + (d4 << 2));
#pragma unroll
            for (int j = 0; j < 4; j++)
                kv[j] = *(const float4*)(Ks + (txx + (j << 4)) * P + (d4 << 2));
#pragma unroll
            for (int i = 0; i < 4; i++)
#pragma unroll
                for (int j = 0; j < 4; j++)
                    s[i][j] += a[i].x * kv[j].x + a[i].y * kv[j].y +
                               a[i].z * kv[j].z + a[i].w * kv[j].w;
        }

#pragma unroll
        for (int i = 0; i < 4; i++) {
            float tm = -1e30f;
#pragma unroll
            for (int j = 0; j < 4; j++) {
                float bv = bb[(r0 + i) * 256 + kt * 64 + txx + (j << 4)];
                s[i][j] = fmaf(s[i][j], 0.125f, bv);
                tm = fmaxf(tm, s[i][j]);
            }
            tm = fmaxf(tm, __shfl_xor_sync(0xffffffffu, tm, 1));
            tm = fmaxf(tm, __shfl_xor_sync(0xffffffffu, tm, 2));
            tm = fmaxf(tm, __shfl_xor_sync(0xffffffffu, tm, 4));
            tm = fmaxf(tm, __shfl_xor_sync(0xffffffffu, tm, 8));
            float mn = fmaxf(m[i], tm);
            float corr = __expf(m[i] - mn);
            m[i] = mn;
            float ps = 0.f;
#pragma unroll
            for (int j = 0; j < 4; j++) {
                s[i][j] = __expf(s[i][j] - mn);
                ps += s[i][j];
            }
            ps += __shfl_xor_sync(0xffffffffu, ps, 1);
            ps += __shfl_xor_sync(0xffffffffu, ps, 2);
            ps += __shfl_xor_sync(0xffffffffu, ps, 4);
            ps += __shfl_xor_sync(0xffffffffu, ps, 8);
            lsum[i] = lsum[i] * corr + ps;
#pragma unroll
            for (int j = 0; j < 4; j++) o[i][j] *= corr;
        }

#pragma unroll
        for (int j = 0; j < 4; j++)
#pragma unroll
            for (int i = 0; i < 4; i++)
                Ss[(txx + (j << 4)) * P + r0 + i] = s[i][j];
        __syncthreads();

#pragma unroll 8
        for (int k = 0; k < 64; k++) {
            float4 pv = *(const float4*)(Ss + k * P + r0);
            float4 vv = *(const float4*)(Vs + k * P + (txx << 2));
            o[0][0] += pv.x * vv.x; o[0][1] += pv.x * vv.y; o[0][2] += pv.x * vv.z; o[0][3] += pv.x * vv.w;
            o[1][0] += pv.y * vv.x; o[1][1] += pv.y * vv.y; o[1][2] += pv.y * vv.z; o[1][3] += pv.y * vv.w;
            o[2][0] += pv.z * vv.x; o[2][1] += pv.z * vv.y; o[2][2] += pv.z * vv.z; o[2][3] += pv.z * vv.w;
            o[3][0] += pv.w * vv.x; o[3][1] += pv.w * vv.y; o[3][2] += pv.w * vv.z; o[3][3] += pv.w * vv.w;
        }
    }

    float* og = attn_out + (size_t)(b * 256 + q0) * 768 + h * 64 + (txx << 2);
#pragma unroll
    for (int i = 0; i < 4; i++) {
        float inv = 1.0f / lsum[i];
        float4 w = make_float4(o[i][0] * inv, o[i][1] * inv,
                               o[i][2] * inv, o[i][3] * inv);
        *(float4*)(og + (size_t)(r0 + i) * 768) = w;
    }
}

// ---------------------------------------------------------------------------
extern "C" void kernel_launch(void* const* d_in, const int* in_sizes, int n_in,
                              void* d_out, int out_size)
{
    const float* x     = (const float*)d_in[0];
    const float* Wqkv  = (const float*)d_in[1];
    const float* bqkv  = (const float*)d_in[2];
    const float* Wout  = (const float*)d_in[3];
    const float* bout  = (const float*)d_in[4];
    const float* table = (const float*)d_in[5];
    const int*   ids   = (const int*)d_in[6];
    float* out = (float*)d_out;

    float *qkv, *attn, *bias;
    bf16 *ah, *al, *bqh, *bql, *boh, *bol;
    cudaGetSymbolAddress((void**)&qkv,  g_qkv);
    cudaGetSymbolAddress((void**)&attn, g_attn);
    cudaGetSymbolAddress((void**)&bias, g_bias);
    cudaGetSymbolAddress((void**)&ah,   g_ah);
    cudaGetSymbolAddress((void**)&al,   g_al);
    cudaGetSymbolAddress((void**)&bqh,  g_bqh);
    cudaGetSymbolAddress((void**)&bql,  g_bql);
    cudaGetSymbolAddress((void**)&boh,  g_boh);
    cudaGetSymbolAddress((void**)&bol,  g_bol);

    const int ATTN_SMEM = 4 * 64 * 68 * 4;
    cudaFuncSetAttribute(attn_kernel,
                         cudaFuncAttributeMaxDynamicSharedMemorySize, ATTN_SMEM);
    cudaFuncSetAttribute(hgemm_kernel,
                         cudaFuncAttributeMaxDynamicSharedMemorySize, GSM);

    // 0) weights: split + transpose to [N,K] bf16 hi/lo
    split_transpose_kernel<<<dim3(2304 / 32, 768 / 32), dim3(32, 8)>>>(
        Wqkv, bqh, bql, 768, 2304);
    split_transpose_kernel<<<dim3(768 / 32, 768 / 32), dim3(32, 8)>>>(
        Wout, boh, bol, 768, 768);

    // 1) dense rel-pos bias
    bias_gather_kernel<<<256, 256>>>(ids, table, bias);

    // 2) split x -> bf16 hi/lo
    split_kernel<<<25165824 / 4 / 256, 256>>>(x, ah, al, 25165824 / 4);

    // 3) QKV projection (split-bf16 HMMA)
    hgemm_kernel<<<dim3(2304 / 128, 32768 / 128), 256, GSM>>>(
        ah, al, bqh, bql, bqkv, qkv, 32768, 2304, 768);

    // 4) fused attention
    attn_kernel<<<dim3(4, 12, 128), 256, ATTN_SMEM>>>(qkv, bias, attn);

    // 5) split attn -> bf16 hi/lo (reuse ah/al)
    split_kernel<<<25165824 / 4 / 256, 256>>>(attn, ah, al, 25165824 / 4);

    // 6) output projection
    hgemm_kernel<<<dim3(768 / 128, 32768 / 128), 256, GSM>>>(
        ah, al, boh, bol, bout, out, 32768, 768, 768);
}